// round 1
// baseline (speedup 1.0000x reference)
#include <cuda_runtime.h>
#include <cuda_bf16.h>
#include <cstdint>

// Dequant: out[r][c] = (float)q[r][c] * row_stats[r] * (1/127)
// ROWS = COLS = 8192. Input int32 (values in [-127,127]), output float32.
// Pure HBM-bound streaming kernel: 256 MiB in + 256 MiB out.
//
// Vectorized: each thread handles one int4 (4 int32) -> one float4.
// 8192 cols / 4 = 2048 int4 per row -> row = vec_idx >> 11 (exact power of 2).

#define COLS 8192
#define VECS_PER_ROW (COLS / 4)      // 2048
#define ROW_SHIFT 11                  // log2(2048)

__global__ void __launch_bounds__(256, 8)
dequant_kernel(const int4* __restrict__ q,
               const float* __restrict__ row_stats,
               float4* __restrict__ out,
               int total_vecs)
{
    int i = blockIdx.x * blockDim.x + threadIdx.x;
    if (i >= total_vecs) return;

    int row = i >> ROW_SHIFT;
    float scale = __ldg(&row_stats[row]) * (1.0f / 127.0f);

    int4 v = q[i];
    float4 r;
    r.x = (float)v.x * scale;
    r.y = (float)v.y * scale;
    r.z = (float)v.z * scale;
    r.w = (float)v.w * scale;
    out[i] = r;
}

extern "C" void kernel_launch(void* const* d_in, const int* in_sizes, int n_in,
                              void* d_out, int out_size)
{
    const int4*  q         = (const int4*)d_in[0];       // quantized_param int32 [8192,8192]
    const float* row_stats = (const float*)d_in[1];      // [8192] fp32
    float4*      out       = (float4*)d_out;

    int total_vecs = out_size / 4;                        // 8192*8192/4 = 16777216
    int threads = 256;
    int blocks  = (total_vecs + threads - 1) / threads;   // 65536

    dequant_kernel<<<blocks, threads>>>(q, row_stats, out, total_vecs);
}

// round 2
// speedup vs baseline: 1.0363x; 1.0363x over previous
#include <cuda_runtime.h>
#include <cuda_bf16.h>
#include <cstdint>

// Dequant: out[r][c] = (float)q[r][c] * row_stats[r] * (1/127)
// ROWS = COLS = 8192, int32 in -> fp32 out. Pure streaming: 512 MiB total.
//
// R2: MLP batching (4 independent int4 loads issued back-to-back per thread)
// + streaming cache hints (__ldcs / __stcs, evict-first: zero reuse).
// Block covers 256*4 = 1024 contiguous int4 vecs; 16384 blocks exactly cover
// 16777216 vecs (no tail, no bounds checks on the hot path).

#define COLS 8192
#define ROW_SHIFT 11                 // log2(8192/4) : int4-vec index -> row
#define VPT 4                        // vectors per thread

__global__ void __launch_bounds__(256, 8)
dequant_kernel(const int4* __restrict__ q,
               const float* __restrict__ row_stats,
               float4* __restrict__ out)
{
    const int base = blockIdx.x * (256 * VPT) + threadIdx.x;

    // Front-batch all loads: 4 independent LDG.E.128 in flight (MLP=4).
    int4 v[VPT];
#pragma unroll
    for (int j = 0; j < VPT; j++)
        v[j] = __ldcs(&q[base + j * 256]);

    // Per-vec row scale (row_stats is tiny, L1-resident; __ldg read-only path).
    float s[VPT];
#pragma unroll
    for (int j = 0; j < VPT; j++) {
        int idx = base + j * 256;
        s[j] = __ldg(&row_stats[idx >> ROW_SHIFT]) * (1.0f / 127.0f);
    }

#pragma unroll
    for (int j = 0; j < VPT; j++) {
        float4 r;
        r.x = (float)v[j].x * s[j];
        r.y = (float)v[j].y * s[j];
        r.z = (float)v[j].z * s[j];
        r.w = (float)v[j].w * s[j];
        __stcs(&out[base + j * 256], r);
    }
}

extern "C" void kernel_launch(void* const* d_in, const int* in_sizes, int n_in,
                              void* d_out, int out_size)
{
    const int4*  q         = (const int4*)d_in[0];   // int32 [8192,8192]
    const float* row_stats = (const float*)d_in[1];  // fp32  [8192]
    float4*      out       = (float4*)d_out;

    const int total_vecs = out_size / 4;             // 16777216
    const int threads = 256;
    const int blocks  = total_vecs / (threads * VPT); // 16384, exact

    dequant_kernel<<<blocks, threads>>>(q, row_stats, out);
}